// round 9
// baseline (speedup 1.0000x reference)
#include <cuda_runtime.h>
#include <cstdint>

// ---------------------------------------------------------------------------
// Problem constants
// ---------------------------------------------------------------------------
#define B_SZ 8192
#define H_SZ 1024
#define K_TOT 2048       // 1024 (x/Wih) + 1024 (hx/Whh)
#define N_TOT 4096       // 4 gates * H

// GEMM tiling
#define BM 256
#define BN 128
#define BK 64            // 64 int8 per k-iter
#define NSTAGE 3         // 3 stages -> 92160 B smem -> 2 CTAs per SM

// smem: rows of 64 data bytes + 16 pad = 80 B pitch (conflict-free ldmatrix)
#define A_BYTES (BM * 80)   // 20480
#define B_BYTES (BN * 80)   // 10240
#define STAGE_BYTES (A_BYTES + B_BYTES)          // 30720
#define GEMM_SMEM (NSTAGE * STAGE_BYTES)         // 92160

// ---------------------------------------------------------------------------
// Scratch (device globals; no allocations allowed)
// Row layout: A row = [A1 (2048 B) | A0 (2048 B)], B row = [B1 | B0]
// ---------------------------------------------------------------------------
__device__ signed char g_Aq[(size_t)B_SZ * 4096];
__device__ signed char g_Bq[(size_t)N_TOT * 4096];
__device__ float       g_wa[B_SZ];
__device__ float       g_wb[N_TOT];
__device__ float       g_gates[(size_t)B_SZ * N_TOT];

// ---------------------------------------------------------------------------
// PTX helpers
// ---------------------------------------------------------------------------
__device__ __forceinline__ uint32_t smem_u32(const void* p) {
    uint32_t r;
    asm("{ .reg .u64 t; cvta.to.shared.u64 t, %1; cvt.u32.u64 %0, t; }"
        : "=r"(r) : "l"(p));
    return r;
}
__device__ __forceinline__ void cp16(uint32_t dst, const void* src) {
    asm volatile("cp.async.cg.shared.global [%0], [%1], 16;" :: "r"(dst), "l"(src));
}
__device__ __forceinline__ void cp_commit() {
    asm volatile("cp.async.commit_group;" ::: "memory");
}
template <int N> __device__ __forceinline__ void cp_wait() {
    asm volatile("cp.async.wait_group %0;" :: "n"(N) : "memory");
}
__device__ __forceinline__ void ldm_x4(uint32_t& r0, uint32_t& r1,
                                       uint32_t& r2, uint32_t& r3, uint32_t addr) {
    asm volatile("ldmatrix.sync.aligned.m8n8.x4.shared.b16 {%0,%1,%2,%3}, [%4];"
                 : "=r"(r0), "=r"(r1), "=r"(r2), "=r"(r3) : "r"(addr));
}
__device__ __forceinline__ void mma_s8(int* c, const uint32_t* a,
                                       uint32_t b0, uint32_t b1) {
    asm volatile(
        "mma.sync.aligned.m16n8k32.row.col.s32.s8.s8.s32 "
        "{%0,%1,%2,%3}, {%4,%5,%6,%7}, {%8,%9}, {%0,%1,%2,%3};"
        : "+r"(c[0]), "+r"(c[1]), "+r"(c[2]), "+r"(c[3])
        : "r"(a[0]), "r"(a[1]), "r"(a[2]), "r"(a[3]), "r"(b0), "r"(b1));
}

// ---------------------------------------------------------------------------
// Conversion: fp32 row -> per-row-scaled 2-digit int8 (a ~= w*(a1 + a0/256))
// One block (256 threads) per row; row = [first(1024) | second(1024)].
// ---------------------------------------------------------------------------
__device__ __forceinline__ void quant4(const float4& v, float inv,
                                       uint32_t& p1, uint32_t& p0) {
    float vv[4] = {v.x, v.y, v.z, v.w};
    p1 = 0; p0 = 0;
#pragma unroll
    for (int i = 0; i < 4; i++) {
        float q = vv[i] * inv;
        int q1 = __float2int_rn(q);
        int q0 = __float2int_rn((q - (float)q1) * 256.0f);
        q0 = max(-127, min(127, q0));
        p1 |= ((uint32_t)(q1 & 0xff)) << (8 * i);
        p0 |= ((uint32_t)(q0 & 0xff)) << (8 * i);
    }
}

__global__ __launch_bounds__(256) void convert_rows_kernel(
    const float* __restrict__ first, const float* __restrict__ second,
    signed char* __restrict__ dst, float* __restrict__ wrow)
{
    __shared__ float shm[9];
    const int row = blockIdx.x;
    const int t   = threadIdx.x;

    float4 vx = *(const float4*)(first  + (size_t)row * H_SZ + t * 4);
    float4 vh = *(const float4*)(second + (size_t)row * H_SZ + t * 4);

    float m = fmaxf(fmaxf(fabsf(vx.x), fabsf(vx.y)), fmaxf(fabsf(vx.z), fabsf(vx.w)));
    m = fmaxf(m, fmaxf(fmaxf(fabsf(vh.x), fabsf(vh.y)),
                       fmaxf(fabsf(vh.z), fabsf(vh.w))));
#pragma unroll
    for (int o = 16; o > 0; o >>= 1)
        m = fmaxf(m, __shfl_xor_sync(0xffffffff, m, o));
    if ((t & 31) == 0) shm[t >> 5] = m;
    __syncthreads();
    if (t == 0) {
        float mm = 0.f;
#pragma unroll
        for (int i = 0; i < 8; i++) mm = fmaxf(mm, shm[i]);
        shm[8] = mm;
        wrow[row] = mm * (1.0f / 127.0f);
    }
    __syncthreads();
    const float mv  = shm[8];
    const float inv = (mv > 0.f) ? 127.0f / mv : 0.0f;

    uint32_t p1, p0;
    signed char* drow = dst + (size_t)row * 4096;
    quant4(vx, inv, p1, p0);
    *(uint32_t*)(drow + t * 4)        = p1;   // A1, first half
    *(uint32_t*)(drow + 2048 + t * 4) = p0;   // A0, first half
    quant4(vh, inv, p1, p0);
    *(uint32_t*)(drow + 1024 + t * 4) = p1;   // A1, second half
    *(uint32_t*)(drow + 3072 + t * 4) = p0;   // A0, second half
}

// ---------------------------------------------------------------------------
// IMMA GEMM phases.
// PHASE 1: G1 = A1 @ B1^T (K bytes 0..2047), store float to g_gates.
// PHASE 2: G2 = A0@B1 + A1@B0 (K 4096, A rotated by 2048), combine:
//          gates = wa*wb*(G1 + G2/256)
// CTA 256x128, 512 threads, 16 warps (8x2), warp tile 32x64.
// 3-stage cp.async pipeline (2 CTAs/SM), one barrier per iteration.
// ---------------------------------------------------------------------------
template <int PHASE>
__global__ __launch_bounds__(512, 2) void gemm_imma_kernel()
{
    constexpr int ITERS = (PHASE == 1) ? 32 : 64;
    extern __shared__ char smem[];
    const uint32_t sbase = smem_u32(smem);

    const int tid  = threadIdx.x;
    const int lane = tid & 31;
    const int wid  = tid >> 5;
    const int m_warp = (wid >> 1) * 32;
    const int n_warp = (wid & 1) * 64;

    const int m0 = blockIdx.y * BM;
    const int n0 = blockIdx.x * BN;

    // global-load indexing (16B quads; smem pitch 80B, 4 quads/row)
    const int ac0 = tid * 2, ac1 = tid * 2 + 1;
    const int ar0 = ac0 >> 2, ak0 = ac0 & 3;
    const int ar1 = ac1 >> 2, ak1 = ac1 & 3;
    const int br  = tid >> 2, bk = tid & 3;

    const signed char* gA0 = g_Aq + (size_t)(m0 + ar0) * 4096 + ak0 * 16;
    const signed char* gA1 = g_Aq + (size_t)(m0 + ar1) * 4096 + ak1 * 16;
    const signed char* gB  = g_Bq + (size_t)(n0 + br)  * 4096 + bk  * 16;
    const uint32_t sA0 = (uint32_t)(ar0 * 80 + ak0 * 16);
    const uint32_t sA1 = (uint32_t)(ar1 * 80 + ak1 * 16);
    const uint32_t sB  = (uint32_t)(br * 80 + bk * 16) + A_BYTES;

    auto kbA = [&](int it) -> int {
        if (PHASE == 1) return it * BK;
        return (it < 32) ? 2048 + it * BK : (it - 32) * BK;  // [A0 | A1]
    };
    auto kbB = [&](int it) -> int {
        return it * BK;                                       // [B1 | B0] linear
    };

    // stage slot: it % 3
    auto issue_stage = [&](int it) {
        const uint32_t stb = sbase + (uint32_t)(it % NSTAGE) * STAGE_BYTES;
        const int ka = kbA(it), kb = kbB(it);
        cp16(stb + sA0, gA0 + ka);
        cp16(stb + sA1, gA1 + ka);
        cp16(stb + sB,  gB  + kb);
        cp_commit();
    };

    int acc[2][8][4];
#pragma unroll
    for (int i = 0; i < 2; i++)
#pragma unroll
        for (int j = 0; j < 8; j++)
#pragma unroll
            for (int q = 0; q < 4; q++) acc[i][j][q] = 0;

    issue_stage(0);
    issue_stage(1);

    // ldmatrix address components (fixed per thread)
    const int a_row = (lane & 15);
    const int a_chk = (lane >> 4);
    const int b_row = ((lane >> 4) << 3) + (lane & 7);
    const int b_chk = (lane >> 3) & 1;

    const uint32_t aoff = (uint32_t)((m_warp + a_row) * 80 + a_chk * 16);
    const uint32_t boff = (uint32_t)((n_warp + b_row) * 80 + b_chk * 16) + A_BYTES;

    for (int it = 0; it < ITERS; ++it) {
        cp_wait<NSTAGE - 2>();        // stage `it` data arrived (<=1 group pending)
        __syncthreads();              // all warps finished slot (it+2)%3's old data
        if (it + 2 < ITERS) issue_stage(it + 2);
        else cp_commit();             // keep group counting aligned

        const uint32_t stb = sbase + (uint32_t)(it % NSTAGE) * STAGE_BYTES;

        uint32_t a[2][4], b0[4][4], b1[4][4];
#pragma unroll
        for (int am = 0; am < 2; ++am)
            ldm_x4(a[am][0], a[am][1], a[am][2], a[am][3],
                   stb + aoff + (uint32_t)(am * 16 * 80));
#pragma unroll
        for (int bn = 0; bn < 4; ++bn)
            ldm_x4(b0[bn][0], b0[bn][1], b0[bn][2], b0[bn][3],
                   stb + boff + (uint32_t)(bn * 16 * 80));
#pragma unroll
        for (int bn = 0; bn < 4; ++bn)
            ldm_x4(b1[bn][0], b1[bn][1], b1[bn][2], b1[bn][3],
                   stb + boff + (uint32_t)(bn * 16 * 80 + 32));
#pragma unroll
        for (int am = 0; am < 2; ++am)
#pragma unroll
            for (int j = 0; j < 8; ++j)
                mma_s8(acc[am][j], a[am], b0[j >> 1][(j & 1) * 2],
                       b0[j >> 1][(j & 1) * 2 + 1]);
#pragma unroll
        for (int am = 0; am < 2; ++am)
            ldm_x4(a[am][0], a[am][1], a[am][2], a[am][3],
                   stb + aoff + (uint32_t)(am * 16 * 80 + 32));
#pragma unroll
        for (int am = 0; am < 2; ++am)
#pragma unroll
            for (int j = 0; j < 8; ++j)
                mma_s8(acc[am][j], a[am], b1[j >> 1][(j & 1) * 2],
                       b1[j >> 1][(j & 1) * 2 + 1]);
    }

    // epilogue
    const int r_base = lane >> 2;
    const int c_base = (lane & 3) * 2;
#pragma unroll
    for (int am = 0; am < 2; ++am) {
        const int row0 = m0 + m_warp + am * 16 + r_base;
        if (PHASE == 1) {
#pragma unroll
            for (int j = 0; j < 8; ++j) {
                const int col = n0 + n_warp + j * 8 + c_base;
                *(float2*)(g_gates + (size_t)row0 * N_TOT + col) =
                    make_float2((float)acc[am][j][0], (float)acc[am][j][1]);
                *(float2*)(g_gates + (size_t)(row0 + 8) * N_TOT + col) =
                    make_float2((float)acc[am][j][2], (float)acc[am][j][3]);
            }
        } else {
            const float wa0 = g_wa[row0];
            const float wa1 = g_wa[row0 + 8];
#pragma unroll
            for (int j = 0; j < 8; ++j) {
                const int col = n0 + n_warp + j * 8 + c_base;
                float2 wb = *(const float2*)(g_wb + col);
                float* p0 = g_gates + (size_t)row0 * N_TOT + col;
                float* p1 = g_gates + (size_t)(row0 + 8) * N_TOT + col;
                float2 g0 = *(float2*)p0;
                float2 g1 = *(float2*)p1;
                g0.x = wa0 * wb.x * (g0.x + (float)acc[am][j][0] * (1.0f / 256.0f));
                g0.y = wa0 * wb.y * (g0.y + (float)acc[am][j][1] * (1.0f / 256.0f));
                g1.x = wa1 * wb.x * (g1.x + (float)acc[am][j][2] * (1.0f / 256.0f));
                g1.y = wa1 * wb.y * (g1.y + (float)acc[am][j][3] * (1.0f / 256.0f));
                *(float2*)p0 = g0;
                *(float2*)p1 = g1;
            }
        }
    }
}

// ---------------------------------------------------------------------------
// LSTM epilogue: one block per batch row (unchanged)
// ---------------------------------------------------------------------------
__device__ __forceinline__ float sigmoidf_(float x) { return 1.0f / (1.0f + __expf(-x)); }

__device__ __forceinline__ void block_ln_stats(float s, float ss, float* shm,
                                               float& mean, float& rstd)
{
    const int lane = threadIdx.x & 31;
    const int warp = threadIdx.x >> 5;
#pragma unroll
    for (int o = 16; o > 0; o >>= 1) {
        s  += __shfl_xor_sync(0xffffffff, s,  o);
        ss += __shfl_xor_sync(0xffffffff, ss, o);
    }
    if (lane == 0) { shm[warp] = s; shm[8 + warp] = ss; }
    __syncthreads();
    if (threadIdx.x == 0) {
        float ts = 0.f, tss = 0.f;
#pragma unroll
        for (int i = 0; i < 8; i++) { ts += shm[i]; tss += shm[8 + i]; }
        shm[16] = ts; shm[17] = tss;
    }
    __syncthreads();
    const float ts = shm[16], tss = shm[17];
    mean = ts * (1.0f / 1024.0f);
    float var = tss * (1.0f / 1024.0f) - mean * mean;
    rstd = rsqrtf(var + 1e-5f);
    __syncthreads();
}

__global__ __launch_bounds__(256) void lstm_epilogue_kernel(
    const float* __restrict__ cx,
    const float* __restrict__ bias_ih, const float* __restrict__ bias_hh,
    const float* __restrict__ ln_i_g,  const float* __restrict__ ln_i_b,
    const float* __restrict__ ln_f_g,  const float* __restrict__ ln_f_b,
    const float* __restrict__ ln_c_g,  const float* __restrict__ ln_c_b,
    const float* __restrict__ ln_cy_g, const float* __restrict__ ln_cy_b,
    const float* __restrict__ ln_o_g,  const float* __restrict__ ln_o_b,
    float* __restrict__ hy_out, float* __restrict__ cy_out)
{
    __shared__ float shm[18];
    const int b   = blockIdx.x;
    const int tid = threadIdx.x;
    const int h4  = tid * 4;

    const float* grow = g_gates + (size_t)b * N_TOT;

    float4 gv[4];
#pragma unroll
    for (int q = 0; q < 4; q++) {
        const int col = q * H_SZ + h4;
        float4 v  = *(const float4*)(grow + col);
        float4 bi = *(const float4*)(bias_ih + col);
        float4 bh = *(const float4*)(bias_hh + col);
        v.x += bi.x + bh.x; v.y += bi.y + bh.y;
        v.z += bi.z + bh.z; v.w += bi.w + bh.w;
        gv[q] = v;
    }

    const float* gam[4] = { ln_i_g, ln_f_g, ln_c_g, ln_o_g };
    const float* bet[4] = { ln_i_b, ln_f_b, ln_c_b, ln_o_b };
    float4 act[4];
#pragma unroll
    for (int q = 0; q < 4; q++) {
        float4 v = gv[q];
        float s  = v.x + v.y + v.z + v.w;
        float ss = v.x * v.x + v.y * v.y + v.z * v.z + v.w * v.w;
        float mean, rstd;
        block_ln_stats(s, ss, shm, mean, rstd);
        float4 g4 = *(const float4*)(gam[q] + h4);
        float4 b4 = *(const float4*)(bet[q] + h4);
        float4 n;
        n.x = (v.x - mean) * rstd * g4.x + b4.x;
        n.y = (v.y - mean) * rstd * g4.y + b4.y;
        n.z = (v.z - mean) * rstd * g4.z + b4.z;
        n.w = (v.w - mean) * rstd * g4.w + b4.w;
        if (q == 2) {
            n.x = tanhf(n.x); n.y = tanhf(n.y); n.z = tanhf(n.z); n.w = tanhf(n.w);
        } else {
            n.x = sigmoidf_(n.x); n.y = sigmoidf_(n.y);
            n.z = sigmoidf_(n.z); n.w = sigmoidf_(n.w);
        }
        act[q] = n;
    }

    float4 cxv = *(const float4*)(cx + (size_t)b * H_SZ + h4);
    float4 t;
    t.x = act[1].x * cxv.x + act[0].x * act[2].x;
    t.y = act[1].y * cxv.y + act[0].y * act[2].y;
    t.z = act[1].z * cxv.z + act[0].z * act[2].z;
    t.w = act[1].w * cxv.w + act[0].w * act[2].w;

    {
        float s  = t.x + t.y + t.z + t.w;
        float ss = t.x * t.x + t.y * t.y + t.z * t.z + t.w * t.w;
        float mean, rstd;
        block_ln_stats(s, ss, shm, mean, rstd);
        float4 g4 = *(const float4*)(ln_cy_g + h4);
        float4 b4 = *(const float4*)(ln_cy_b + h4);
        float4 cyv;
        cyv.x = (t.x - mean) * rstd * g4.x + b4.x;
        cyv.y = (t.y - mean) * rstd * g4.y + b4.y;
        cyv.z = (t.z - mean) * rstd * g4.z + b4.z;
        cyv.w = (t.w - mean) * rstd * g4.w + b4.w;

        float4 hyv;
        hyv.x = act[3].x * tanhf(cyv.x);
        hyv.y = act[3].y * tanhf(cyv.y);
        hyv.z = act[3].z * tanhf(cyv.z);
        hyv.w = act[3].w * tanhf(cyv.w);

        *(float4*)(cy_out + (size_t)b * H_SZ + h4) = cyv;
        *(float4*)(hy_out + (size_t)b * H_SZ + h4) = hyv;
    }
}

// ---------------------------------------------------------------------------
// Launch
// ---------------------------------------------------------------------------
extern "C" void kernel_launch(void* const* d_in, const int* in_sizes, int n_in,
                              void* d_out, int out_size)
{
    const float* x        = (const float*)d_in[0];
    const float* hx       = (const float*)d_in[1];
    const float* cx       = (const float*)d_in[2];
    const float* wih      = (const float*)d_in[3];
    const float* whh      = (const float*)d_in[4];
    const float* bias_ih  = (const float*)d_in[5];
    const float* bias_hh  = (const float*)d_in[6];
    const float* ln_i_g   = (const float*)d_in[7];
    const float* ln_i_b   = (const float*)d_in[8];
    const float* ln_f_g   = (const float*)d_in[9];
    const float* ln_f_b   = (const float*)d_in[10];
    const float* ln_c_g   = (const float*)d_in[11];
    const float* ln_c_b   = (const float*)d_in[12];
    const float* ln_cy_g  = (const float*)d_in[13];
    const float* ln_cy_b  = (const float*)d_in[14];
    const float* ln_o_g   = (const float*)d_in[15];
    const float* ln_o_b   = (const float*)d_in[16];

    float* out = (float*)d_out;
    float* hy  = out;
    float* cy  = out + (size_t)B_SZ * H_SZ;

    static bool attr_set = false;
    if (!attr_set) {
        cudaFuncSetAttribute(gemm_imma_kernel<1>,
                             cudaFuncAttributeMaxDynamicSharedMemorySize, GEMM_SMEM);
        cudaFuncSetAttribute(gemm_imma_kernel<2>,
                             cudaFuncAttributeMaxDynamicSharedMemorySize, GEMM_SMEM);
        attr_set = true;
    }

    // Quantize A rows ([x|hx], 8192 rows) and B rows ([Wih|Whh], 4096 rows)
    {
        signed char* Aq; cudaGetSymbolAddress((void**)&Aq, g_Aq);
        signed char* Bq; cudaGetSymbolAddress((void**)&Bq, g_Bq);
        float* wa; cudaGetSymbolAddress((void**)&wa, g_wa);
        float* wb; cudaGetSymbolAddress((void**)&wb, g_wb);
        convert_rows_kernel<<<B_SZ, 256>>>(x, hx, Aq, wa);
        convert_rows_kernel<<<N_TOT, 256>>>(wih, whh, Bq, wb);
    }

    dim3 ggrid(N_TOT / BN, B_SZ / BM);   // (32, 32)
    gemm_imma_kernel<1><<<ggrid, 512, GEMM_SMEM>>>();
    gemm_imma_kernel<2><<<ggrid, 512, GEMM_SMEM>>>();

    lstm_epilogue_kernel<<<B_SZ, 256>>>(cx, bias_ih, bias_hh,
                                        ln_i_g, ln_i_b, ln_f_g, ln_f_b,
                                        ln_c_g, ln_c_b, ln_cy_g, ln_cy_b,
                                        ln_o_g, ln_o_b, hy, cy);
}

// round 10
// speedup vs baseline: 3.2092x; 3.2092x over previous
#include <cuda_runtime.h>
#include <cstdint>

// ---------------------------------------------------------------------------
// Problem constants
// ---------------------------------------------------------------------------
#define B_SZ 8192
#define H_SZ 1024
#define K_TOT 2048       // 1024 (x/Wih) + 1024 (hx/Whh)
#define N_TOT 4096       // 4 gates * H

// GEMM tiling: CTA 128x128, 256 threads (8 warps, 4x2), warp tile 32x64.
// 256 thr * 128 regs = 32K regs -> 2 CTAs per SM (64K regfile).
#define BM 128
#define BN 128
#define BK 64            // 64 int8 per k-iter
#define NSTAGE 4

// smem: rows of 64 data bytes + 16 pad = 80 B pitch (conflict-free ldmatrix)
#define A_BYTES (BM * 80)   // 10240
#define B_BYTES (BN * 80)   // 10240
#define STAGE_BYTES (A_BYTES + B_BYTES)          // 20480
#define GEMM_SMEM (NSTAGE * STAGE_BYTES)         // 81920  (x2 CTAs = 163840)

// ---------------------------------------------------------------------------
// Scratch (device globals; no allocations allowed)
// Row layout: A row = [A1 (2048 B) | A0 (2048 B)], B row = [B1 | B0]
// ---------------------------------------------------------------------------
__device__ signed char g_Aq[(size_t)B_SZ * 4096];
__device__ signed char g_Bq[(size_t)N_TOT * 4096];
__device__ float       g_wa[B_SZ];
__device__ float       g_wb[N_TOT];
__device__ float       g_gates[(size_t)B_SZ * N_TOT];

// ---------------------------------------------------------------------------
// PTX helpers
// ---------------------------------------------------------------------------
__device__ __forceinline__ uint32_t smem_u32(const void* p) {
    uint32_t r;
    asm("{ .reg .u64 t; cvta.to.shared.u64 t, %1; cvt.u32.u64 %0, t; }"
        : "=r"(r) : "l"(p));
    return r;
}
__device__ __forceinline__ void cp16(uint32_t dst, const void* src) {
    asm volatile("cp.async.cg.shared.global [%0], [%1], 16;" :: "r"(dst), "l"(src));
}
__device__ __forceinline__ void cp_commit() {
    asm volatile("cp.async.commit_group;" ::: "memory");
}
template <int N> __device__ __forceinline__ void cp_wait() {
    asm volatile("cp.async.wait_group %0;" :: "n"(N) : "memory");
}
__device__ __forceinline__ void ldm_x4(uint32_t& r0, uint32_t& r1,
                                       uint32_t& r2, uint32_t& r3, uint32_t addr) {
    asm volatile("ldmatrix.sync.aligned.m8n8.x4.shared.b16 {%0,%1,%2,%3}, [%4];"
                 : "=r"(r0), "=r"(r1), "=r"(r2), "=r"(r3) : "r"(addr));
}
__device__ __forceinline__ void mma_s8(int* c, const uint32_t* a,
                                       uint32_t b0, uint32_t b1) {
    asm volatile(
        "mma.sync.aligned.m16n8k32.row.col.s32.s8.s8.s32 "
        "{%0,%1,%2,%3}, {%4,%5,%6,%7}, {%8,%9}, {%0,%1,%2,%3};"
        : "+r"(c[0]), "+r"(c[1]), "+r"(c[2]), "+r"(c[3])
        : "r"(a[0]), "r"(a[1]), "r"(a[2]), "r"(a[3]), "r"(b0), "r"(b1));
}

// ---------------------------------------------------------------------------
// Conversion: fp32 row -> per-row-scaled 2-digit int8 (a ~= w*(a1 + a0/256))
// One block (256 threads) per row; row = [first(1024) | second(1024)].
// ---------------------------------------------------------------------------
__device__ __forceinline__ void quant4(const float4& v, float inv,
                                       uint32_t& p1, uint32_t& p0) {
    float vv[4] = {v.x, v.y, v.z, v.w};
    p1 = 0; p0 = 0;
#pragma unroll
    for (int i = 0; i < 4; i++) {
        float q = vv[i] * inv;
        int q1 = __float2int_rn(q);
        int q0 = __float2int_rn((q - (float)q1) * 256.0f);
        q0 = max(-127, min(127, q0));
        p1 |= ((uint32_t)(q1 & 0xff)) << (8 * i);
        p0 |= ((uint32_t)(q0 & 0xff)) << (8 * i);
    }
}

__global__ __launch_bounds__(256) void convert_rows_kernel(
    const float* __restrict__ first, const float* __restrict__ second,
    signed char* __restrict__ dst, float* __restrict__ wrow)
{
    __shared__ float shm[9];
    const int row = blockIdx.x;
    const int t   = threadIdx.x;

    float4 vx = *(const float4*)(first  + (size_t)row * H_SZ + t * 4);
    float4 vh = *(const float4*)(second + (size_t)row * H_SZ + t * 4);

    float m = fmaxf(fmaxf(fabsf(vx.x), fabsf(vx.y)), fmaxf(fabsf(vx.z), fabsf(vx.w)));
    m = fmaxf(m, fmaxf(fmaxf(fabsf(vh.x), fabsf(vh.y)),
                       fmaxf(fabsf(vh.z), fabsf(vh.w))));
#pragma unroll
    for (int o = 16; o > 0; o >>= 1)
        m = fmaxf(m, __shfl_xor_sync(0xffffffff, m, o));
    if ((t & 31) == 0) shm[t >> 5] = m;
    __syncthreads();
    if (t == 0) {
        float mm = 0.f;
#pragma unroll
        for (int i = 0; i < 8; i++) mm = fmaxf(mm, shm[i]);
        shm[8] = mm;
        wrow[row] = mm * (1.0f / 127.0f);
    }
    __syncthreads();
    const float mv  = shm[8];
    const float inv = (mv > 0.f) ? 127.0f / mv : 0.0f;

    uint32_t p1, p0;
    signed char* drow = dst + (size_t)row * 4096;
    quant4(vx, inv, p1, p0);
    *(uint32_t*)(drow + t * 4)        = p1;   // A1, first half
    *(uint32_t*)(drow + 2048 + t * 4) = p0;   // A0, first half
    quant4(vh, inv, p1, p0);
    *(uint32_t*)(drow + 1024 + t * 4) = p1;   // A1, second half
    *(uint32_t*)(drow + 3072 + t * 4) = p0;   // A0, second half
}

// ---------------------------------------------------------------------------
// IMMA GEMM phases.
// PHASE 1: G1 = A1 @ B1^T (K bytes 0..2047), store float to g_gates.
// PHASE 2: G2 = A0@B1 + A1@B0 (K 4096, A rotated by 2048), combine:
//          gates = wa*wb*(G1 + G2/256)
// CTA 128x128, 256 threads, 8 warps (4x2), warp tile 32x64.
// 4-stage cp.async pipeline, one barrier per iteration, 2 CTAs/SM.
// ---------------------------------------------------------------------------
template <int PHASE>
__global__ __launch_bounds__(256, 2) void gemm_imma_kernel()
{
    constexpr int ITERS = (PHASE == 1) ? 32 : 64;
    extern __shared__ char smem[];
    const uint32_t sbase = smem_u32(smem);

    const int tid  = threadIdx.x;
    const int lane = tid & 31;
    const int wid  = tid >> 5;            // 0..7
    const int m_warp = (wid >> 1) * 32;   // 4 warps along M
    const int n_warp = (wid & 1) * 64;    // 2 warps along N

    const int m0 = blockIdx.y * BM;
    const int n0 = blockIdx.x * BN;

    // global-load indexing: 512 A quads + 512 B quads per stage, 4 per thread
    const int ac0 = tid, ac1 = tid + 256;
    const int ar0 = ac0 >> 2, ak0 = ac0 & 3;
    const int ar1 = ac1 >> 2, ak1 = ac1 & 3;

    const signed char* gA0 = g_Aq + (size_t)(m0 + ar0) * 4096 + ak0 * 16;
    const signed char* gA1 = g_Aq + (size_t)(m0 + ar1) * 4096 + ak1 * 16;
    const signed char* gB0 = g_Bq + (size_t)(n0 + ar0) * 4096 + ak0 * 16;
    const signed char* gB1 = g_Bq + (size_t)(n0 + ar1) * 4096 + ak1 * 16;
    const uint32_t sA0 = (uint32_t)(ar0 * 80 + ak0 * 16);
    const uint32_t sA1 = (uint32_t)(ar1 * 80 + ak1 * 16);
    const uint32_t sB0 = (uint32_t)(ar0 * 80 + ak0 * 16) + A_BYTES;
    const uint32_t sB1 = (uint32_t)(ar1 * 80 + ak1 * 16) + A_BYTES;

    auto kbA = [&](int it) -> int {
        if (PHASE == 1) return it * BK;
        return (it < 32) ? 2048 + it * BK : (it - 32) * BK;  // [A0 | A1]
    };
    auto kbB = [&](int it) -> int {
        return it * BK;                                       // [B1 | B0] linear
    };

    auto issue_stage = [&](int it) {
        const uint32_t stb = sbase + (uint32_t)(it & (NSTAGE - 1)) * STAGE_BYTES;
        const int ka = kbA(it), kb = kbB(it);
        cp16(stb + sA0, gA0 + ka);
        cp16(stb + sA1, gA1 + ka);
        cp16(stb + sB0, gB0 + kb);
        cp16(stb + sB1, gB1 + kb);
        cp_commit();
    };

    int acc[2][8][4];
#pragma unroll
    for (int i = 0; i < 2; i++)
#pragma unroll
        for (int j = 0; j < 8; j++)
#pragma unroll
            for (int q = 0; q < 4; q++) acc[i][j][q] = 0;

    issue_stage(0);
    issue_stage(1);
    issue_stage(2);

    // ldmatrix address components (fixed per thread)
    const int a_row = (lane & 15);
    const int a_chk = (lane >> 4);
    const int b_row = ((lane >> 4) << 3) + (lane & 7);
    const int b_chk = (lane >> 3) & 1;

    const uint32_t aoff = (uint32_t)((m_warp + a_row) * 80 + a_chk * 16);
    const uint32_t boff = (uint32_t)((n_warp + b_row) * 80 + b_chk * 16) + A_BYTES;

    for (int it = 0; it < ITERS; ++it) {
        cp_wait<NSTAGE - 2>();        // stage `it` data arrived
        __syncthreads();              // slot (it+3)&3's old data fully consumed
        if (it + 3 < ITERS) issue_stage(it + 3);
        else cp_commit();             // keep group counting aligned

        const uint32_t stb = sbase + (uint32_t)(it & (NSTAGE - 1)) * STAGE_BYTES;

        uint32_t a[2][4], b0[4][4], b1[4][4];
#pragma unroll
        for (int am = 0; am < 2; ++am)
            ldm_x4(a[am][0], a[am][1], a[am][2], a[am][3],
                   stb + aoff + (uint32_t)(am * 16 * 80));
#pragma unroll
        for (int bn = 0; bn < 4; ++bn)
            ldm_x4(b0[bn][0], b0[bn][1], b0[bn][2], b0[bn][3],
                   stb + boff + (uint32_t)(bn * 16 * 80));
#pragma unroll
        for (int bn = 0; bn < 4; ++bn)
            ldm_x4(b1[bn][0], b1[bn][1], b1[bn][2], b1[bn][3],
                   stb + boff + (uint32_t)(bn * 16 * 80 + 32));
#pragma unroll
        for (int am = 0; am < 2; ++am)
#pragma unroll
            for (int j = 0; j < 8; ++j)
                mma_s8(acc[am][j], a[am], b0[j >> 1][(j & 1) * 2],
                       b0[j >> 1][(j & 1) * 2 + 1]);
#pragma unroll
        for (int am = 0; am < 2; ++am)
            ldm_x4(a[am][0], a[am][1], a[am][2], a[am][3],
                   stb + aoff + (uint32_t)(am * 16 * 80 + 32));
#pragma unroll
        for (int am = 0; am < 2; ++am)
#pragma unroll
            for (int j = 0; j < 8; ++j)
                mma_s8(acc[am][j], a[am], b1[j >> 1][(j & 1) * 2],
                       b1[j >> 1][(j & 1) * 2 + 1]);
    }

    // epilogue
    const int r_base = lane >> 2;
    const int c_base = (lane & 3) * 2;
#pragma unroll
    for (int am = 0; am < 2; ++am) {
        const int row0 = m0 + m_warp + am * 16 + r_base;
        if (PHASE == 1) {
#pragma unroll
            for (int j = 0; j < 8; ++j) {
                const int col = n0 + n_warp + j * 8 + c_base;
                *(float2*)(g_gates + (size_t)row0 * N_TOT + col) =
                    make_float2((float)acc[am][j][0], (float)acc[am][j][1]);
                *(float2*)(g_gates + (size_t)(row0 + 8) * N_TOT + col) =
                    make_float2((float)acc[am][j][2], (float)acc[am][j][3]);
            }
        } else {
            const float wa0 = g_wa[row0];
            const float wa1 = g_wa[row0 + 8];
#pragma unroll
            for (int j = 0; j < 8; ++j) {
                const int col = n0 + n_warp + j * 8 + c_base;
                float2 wb = *(const float2*)(g_wb + col);
                float* p0 = g_gates + (size_t)row0 * N_TOT + col;
                float* p1 = g_gates + (size_t)(row0 + 8) * N_TOT + col;
                float2 g0 = *(float2*)p0;
                float2 g1 = *(float2*)p1;
                g0.x = wa0 * wb.x * (g0.x + (float)acc[am][j][0] * (1.0f / 256.0f));
                g0.y = wa0 * wb.y * (g0.y + (float)acc[am][j][1] * (1.0f / 256.0f));
                g1.x = wa1 * wb.x * (g1.x + (float)acc[am][j][2] * (1.0f / 256.0f));
                g1.y = wa1 * wb.y * (g1.y + (float)acc[am][j][3] * (1.0f / 256.0f));
                *(float2*)p0 = g0;
                *(float2*)p1 = g1;
            }
        }
    }
}

// ---------------------------------------------------------------------------
// LSTM epilogue: one block per batch row (unchanged)
// ---------------------------------------------------------------------------
__device__ __forceinline__ float sigmoidf_(float x) { return 1.0f / (1.0f + __expf(-x)); }

__device__ __forceinline__ void block_ln_stats(float s, float ss, float* shm,
                                               float& mean, float& rstd)
{
    const int lane = threadIdx.x & 31;
    const int warp = threadIdx.x >> 5;
#pragma unroll
    for (int o = 16; o > 0; o >>= 1) {
        s  += __shfl_xor_sync(0xffffffff, s,  o);
        ss += __shfl_xor_sync(0xffffffff, ss, o);
    }
    if (lane == 0) { shm[warp] = s; shm[8 + warp] = ss; }
    __syncthreads();
    if (threadIdx.x == 0) {
        float ts = 0.f, tss = 0.f;
#pragma unroll
        for (int i = 0; i < 8; i++) { ts += shm[i]; tss += shm[8 + i]; }
        shm[16] = ts; shm[17] = tss;
    }
    __syncthreads();
    const float ts = shm[16], tss = shm[17];
    mean = ts * (1.0f / 1024.0f);
    float var = tss * (1.0f / 1024.0f) - mean * mean;
    rstd = rsqrtf(var + 1e-5f);
    __syncthreads();
}

__global__ __launch_bounds__(256) void lstm_epilogue_kernel(
    const float* __restrict__ cx,
    const float* __restrict__ bias_ih, const float* __restrict__ bias_hh,
    const float* __restrict__ ln_i_g,  const float* __restrict__ ln_i_b,
    const float* __restrict__ ln_f_g,  const float* __restrict__ ln_f_b,
    const float* __restrict__ ln_c_g,  const float* __restrict__ ln_c_b,
    const float* __restrict__ ln_cy_g, const float* __restrict__ ln_cy_b,
    const float* __restrict__ ln_o_g,  const float* __restrict__ ln_o_b,
    float* __restrict__ hy_out, float* __restrict__ cy_out)
{
    __shared__ float shm[18];
    const int b   = blockIdx.x;
    const int tid = threadIdx.x;
    const int h4  = tid * 4;

    const float* grow = g_gates + (size_t)b * N_TOT;

    float4 gv[4];
#pragma unroll
    for (int q = 0; q < 4; q++) {
        const int col = q * H_SZ + h4;
        float4 v  = *(const float4*)(grow + col);
        float4 bi = *(const float4*)(bias_ih + col);
        float4 bh = *(const float4*)(bias_hh + col);
        v.x += bi.x + bh.x; v.y += bi.y + bh.y;
        v.z += bi.z + bh.z; v.w += bi.w + bh.w;
        gv[q] = v;
    }

    const float* gam[4] = { ln_i_g, ln_f_g, ln_c_g, ln_o_g };
    const float* bet[4] = { ln_i_b, ln_f_b, ln_c_b, ln_o_b };
    float4 act[4];
#pragma unroll
    for (int q = 0; q < 4; q++) {
        float4 v = gv[q];
        float s  = v.x + v.y + v.z + v.w;
        float ss = v.x * v.x + v.y * v.y + v.z * v.z + v.w * v.w;
        float mean, rstd;
        block_ln_stats(s, ss, shm, mean, rstd);
        float4 g4 = *(const float4*)(gam[q] + h4);
        float4 b4 = *(const float4*)(bet[q] + h4);
        float4 n;
        n.x = (v.x - mean) * rstd * g4.x + b4.x;
        n.y = (v.y - mean) * rstd * g4.y + b4.y;
        n.z = (v.z - mean) * rstd * g4.z + b4.z;
        n.w = (v.w - mean) * rstd * g4.w + b4.w;
        if (q == 2) {
            n.x = tanhf(n.x); n.y = tanhf(n.y); n.z = tanhf(n.z); n.w = tanhf(n.w);
        } else {
            n.x = sigmoidf_(n.x); n.y = sigmoidf_(n.y);
            n.z = sigmoidf_(n.z); n.w = sigmoidf_(n.w);
        }
        act[q] = n;
    }

    float4 cxv = *(const float4*)(cx + (size_t)b * H_SZ + h4);
    float4 t;
    t.x = act[1].x * cxv.x + act[0].x * act[2].x;
    t.y = act[1].y * cxv.y + act[0].y * act[2].y;
    t.z = act[1].z * cxv.z + act[0].z * act[2].z;
    t.w = act[1].w * cxv.w + act[0].w * act[2].w;

    {
        float s  = t.x + t.y + t.z + t.w;
        float ss = t.x * t.x + t.y * t.y + t.z * t.z + t.w * t.w;
        float mean, rstd;
        block_ln_stats(s, ss, shm, mean, rstd);
        float4 g4 = *(const float4*)(ln_cy_g + h4);
        float4 b4 = *(const float4*)(ln_cy_b + h4);
        float4 cyv;
        cyv.x = (t.x - mean) * rstd * g4.x + b4.x;
        cyv.y = (t.y - mean) * rstd * g4.y + b4.y;
        cyv.z = (t.z - mean) * rstd * g4.z + b4.z;
        cyv.w = (t.w - mean) * rstd * g4.w + b4.w;

        float4 hyv;
        hyv.x = act[3].x * tanhf(cyv.x);
        hyv.y = act[3].y * tanhf(cyv.y);
        hyv.z = act[3].z * tanhf(cyv.z);
        hyv.w = act[3].w * tanhf(cyv.w);

        *(float4*)(cy_out + (size_t)b * H_SZ + h4) = cyv;
        *(float4*)(hy_out + (size_t)b * H_SZ + h4) = hyv;
    }
}

// ---------------------------------------------------------------------------
// Launch
// ---------------------------------------------------------------------------
extern "C" void kernel_launch(void* const* d_in, const int* in_sizes, int n_in,
                              void* d_out, int out_size)
{
    const float* x        = (const float*)d_in[0];
    const float* hx       = (const float*)d_in[1];
    const float* cx       = (const float*)d_in[2];
    const float* wih      = (const float*)d_in[3];
    const float* whh      = (const float*)d_in[4];
    const float* bias_ih  = (const float*)d_in[5];
    const float* bias_hh  = (const float*)d_in[6];
    const float* ln_i_g   = (const float*)d_in[7];
    const float* ln_i_b   = (const float*)d_in[8];
    const float* ln_f_g   = (const float*)d_in[9];
    const float* ln_f_b   = (const float*)d_in[10];
    const float* ln_c_g   = (const float*)d_in[11];
    const float* ln_c_b   = (const float*)d_in[12];
    const float* ln_cy_g  = (const float*)d_in[13];
    const float* ln_cy_b  = (const float*)d_in[14];
    const float* ln_o_g   = (const float*)d_in[15];
    const float* ln_o_b   = (const float*)d_in[16];

    float* out = (float*)d_out;
    float* hy  = out;
    float* cy  = out + (size_t)B_SZ * H_SZ;

    static bool attr_set = false;
    if (!attr_set) {
        cudaFuncSetAttribute(gemm_imma_kernel<1>,
                             cudaFuncAttributeMaxDynamicSharedMemorySize, GEMM_SMEM);
        cudaFuncSetAttribute(gemm_imma_kernel<2>,
                             cudaFuncAttributeMaxDynamicSharedMemorySize, GEMM_SMEM);
        attr_set = true;
    }

    // Quantize A rows ([x|hx], 8192 rows) and B rows ([Wih|Whh], 4096 rows)
    {
        signed char* Aq; cudaGetSymbolAddress((void**)&Aq, g_Aq);
        signed char* Bq; cudaGetSymbolAddress((void**)&Bq, g_Bq);
        float* wa; cudaGetSymbolAddress((void**)&wa, g_wa);
        float* wb; cudaGetSymbolAddress((void**)&wb, g_wb);
        convert_rows_kernel<<<B_SZ, 256>>>(x, hx, Aq, wa);
        convert_rows_kernel<<<N_TOT, 256>>>(wih, whh, Bq, wb);
    }

    dim3 ggrid(N_TOT / BN, B_SZ / BM);   // (32, 64) = 2048 CTAs
    gemm_imma_kernel<1><<<ggrid, 256, GEMM_SMEM>>>();
    gemm_imma_kernel<2><<<ggrid, 256, GEMM_SMEM>>>();

    lstm_epilogue_kernel<<<B_SZ, 256>>>(cx, bias_ih, bias_hh,
                                        ln_i_g, ln_i_b, ln_f_g, ln_f_b,
                                        ln_c_g, ln_c_b, ln_cy_g, ln_cy_b,
                                        ln_o_g, ln_o_b, hy, cy);
}